// round 9
// baseline (speedup 1.0000x reference)
#include <cuda_runtime.h>
#include <cuda_fp16.h>
#include <cstdint>

// ---------------- problem dims ----------------
#define NB    8
#define HH    128
#define WW    128
#define CIN   64
#define COUT  128
#define ROWS_PER_VAR (NB*HH*WW)      // 131072
#define ALPHA 0.2f
#define EPS_BN 1e-3f

// ---------------- device globals (no allocs allowed) ----------------
__device__ __align__(16) float  g_fT[9 * COUT * CIN];                 // [uv][o][c] fp32
__device__ __align__(16) __half g_Bh[(size_t)HH * 5 * COUT * CIN];    // [h][vb][o][c] fp16
__device__ __align__(16) __half g_raw[(size_t)2 * ROWS_PER_VAR * COUT]; // fp16 raw GEMM out
__device__ float g_sum[2 * COUT];
__device__ float g_sumsq[2 * COUT];

// ---------------- helpers ----------------
__device__ __forceinline__ uint32_t smem_u32(const void* p) {
    uint32_t a;
    asm("{ .reg .u64 t; cvta.to.shared.u64 t, %1; cvt.u32.u64 %0, t; }" : "=r"(a) : "l"(p));
    return a;
}

__device__ __forceinline__ void ldsm4(uint32_t& r0, uint32_t& r1, uint32_t& r2, uint32_t& r3,
                                      uint32_t addr) {
    asm volatile("ldmatrix.sync.aligned.m8n8.x4.shared.b16 {%0,%1,%2,%3}, [%4];"
                 : "=r"(r0), "=r"(r1), "=r"(r2), "=r"(r3) : "r"(addr));
}

__device__ __forceinline__ void mma16816(float* d, const uint32_t* a, const uint32_t* b) {
    asm volatile("mma.sync.aligned.m16n8k16.row.col.f32.f16.f16.f32 "
                 "{%0,%1,%2,%3}, {%4,%5,%6,%7}, {%8,%9}, {%0,%1,%2,%3};"
                 : "+f"(d[0]), "+f"(d[1]), "+f"(d[2]), "+f"(d[3])
                 : "r"(a[0]), "r"(a[1]), "r"(a[2]), "r"(a[3]), "r"(b[0]), "r"(b[1]));
}

__device__ __forceinline__ uint32_t packh2(float lo, float hi) {
    __half2 t = __floats2half2_rn(lo, hi);
    return *(uint32_t*)&t;
}

__device__ __forceinline__ uint32_t bcasth2(float x) {
    __half h = __float2half_rn(x);
    __half2 t = __half2half2(h);
    return *(uint32_t*)&t;
}

__device__ __forceinline__ uint32_t hmul2u(uint32_t a, uint32_t b) {
    __half2 r = __hmul2(*(__half2*)&a, *(__half2*)&b);
    return *(uint32_t*)&r;
}

__device__ __forceinline__ void cp_async16(uint32_t dst_smem, const void* src) {
    asm volatile("cp.async.cg.shared.global [%0], [%1], 16;"
                 :: "r"(dst_smem), "l"(src) : "memory");
}
#define CP_ASYNC_COMMIT() asm volatile("cp.async.commit_group;" ::: "memory")

__device__ __forceinline__ void stcs16(void* p, uint4 v) {
    asm volatile("st.global.cs.v4.u32 [%0], {%1,%2,%3,%4};"
                 :: "l"(p), "r"(v.x), "r"(v.y), "r"(v.z), "r"(v.w) : "memory");
}
__device__ __forceinline__ uint4 ldcs16(const void* p) {
    uint4 v;
    asm volatile("ld.global.cs.v4.u32 {%0,%1,%2,%3}, [%4];"
                 : "=r"(v.x), "=r"(v.y), "=r"(v.z), "=r"(v.w) : "l"(p));
    return v;
}

// ================= prep 1: transpose filters [uv][c][o] -> g_fT[uv][o][c]; zero stats =====
__global__ void __launch_bounds__(256) prep_T(const float* __restrict__ filters) {
    __shared__ float tile[COUT * 65];
    const int uv = blockIdx.x;          // 0..8
    const int tid = threadIdx.x;
    if (uv == 0) { g_sum[tid] = 0.0f; g_sumsq[tid] = 0.0f; }
    const float* src = filters + (size_t)uv * (CIN * COUT);
#pragma unroll 32
    for (int j = 0; j < 32; ++j) {
        int idx = tid + j * 256;
        tile[(idx & 127) * 65 + (idx >> 7)] = src[idx];
    }
    __syncthreads();
    float* dst = g_fT + (size_t)uv * (COUT * CIN);
#pragma unroll 32
    for (int j = 0; j < 32; ++j) {
        int idx = tid + j * 256;
        dst[idx] = tile[(idx >> 6) * 65 + (idx & 63)];
    }
}

// ================= prep 2: stream per-(h, basis) matrices to fp16 ==================
__global__ void __launch_bounds__(256) prep_B2() {
    const int hb = blockIdx.x;          // h*5 + vb
    const int h = hb / 5;
    const int vb = hb - 5 * h;
    const int tid = threadIdx.x;
    const int v = (vb == 0) ? 0 : ((vb <= 2) ? 1 : 2);
    const bool sinb = (vb == 2) || (vb == 4);

    float c1, s1, c2, s2;
    sincospif((float)h * (1.0f / 64.0f), &s1, &c1);
    sincospif((float)h * (1.0f / 32.0f), &s2, &c2);
    const float w0 = sinb ? 0.0f : 1.0f;
    const float w1 = sinb ? s1 : c1;
    const float w2 = sinb ? s2 : c2;

    const float4* p0 = (const float4*)(g_fT + (size_t)(0 * 3 + v) * (COUT * CIN));
    const float4* p1 = (const float4*)(g_fT + (size_t)(1 * 3 + v) * (COUT * CIN));
    const float4* p2 = (const float4*)(g_fT + (size_t)(2 * 3 + v) * (COUT * CIN));
    __half* dst = g_Bh + (size_t)hb * (COUT * CIN);

#pragma unroll 4
    for (int j = 0; j < 4; ++j) {
        int g = tid + j * 256;
        int f4 = g * 2;
#pragma unroll 2
        for (int q = 0; q < 2; ++q) {
            float4 a = p0[f4 + q];
            float4 b = p1[f4 + q];
            float4 c = p2[f4 + q];
            float r0 = w0 * a.x + w1 * b.x + w2 * c.x;
            float r1 = w0 * a.y + w1 * b.y + w2 * c.y;
            float r2 = w0 * a.z + w1 * b.z + w2 * c.z;
            float r3 = w0 * a.w + w1 * b.w + w2 * c.w;
            *(uint2*)(dst + (size_t)g * 8 + q * 4) =
                make_uint2(packh2(r0, r1), packh2(r2, r3));
        }
    }
}

// ---------------- main smem layout ----------------
#define SMX_XS    0          // 64 rows x 128B fp16 swizzled (sum variant)   = 8192
#define SMX_XD    8192       // 64 rows x 128B fp16 swizzled (dif variant)   = 8192
#define SMX_B     16384      // 5 stages x (128 rows x 128B)                 = 81920
#define SMX_STAT  98304      // 512 floats                                   = 2048
#define SMX_TOTAL 100352
// epilogue staging reuses SMX_B: 2 variants x 64 rows x 272B (16B-aligned pitch!)
#define STG_ROWB  272
#define STG_VARB  (64 * STG_ROWB)

// ================= main: per CTA = (n,h, M-half); all B preloaded, staged epilogue ========
__global__ void __launch_bounds__(256, 2) fourier_main(const float* __restrict__ xr,
                                                       const float* __restrict__ xi) {
    extern __shared__ char smem[];
    float* sStat = (float*)(smem + SMX_STAT);
    const uint32_t sb = smem_u32(smem);

    const int tid = threadIdx.x;
    const int wid = tid >> 5;
    const int l = tid & 31;
    const int v = wid >> 2;             // 0 = real(sum), 1 = imag(dif)
    const int wm = (wid & 3) * 16;      // warp M tile within the 64-row half
    const int bid = blockIdx.x;
    const int b = bid >> 1;             // n*128 + h
    const int mhalf = bid & 1;
    const int h = b & 127;

    sStat[tid] = 0.0f;
    sStat[tid + 256] = 0.0f;

    // ---- preload ALL 5 B stages via cp.async (5 groups) ----
    const __half* BhBase = g_Bh + (size_t)(h * 5) * (COUT * CIN);
#pragma unroll 5
    for (int s = 0; s < 5; ++s) {
        const __half* Bsrc = BhBase + (size_t)s * (COUT * CIN);
        uint32_t sdst = sb + SMX_B + s * 16384;
#pragma unroll 4
        for (int j = 0; j < 4; ++j) {
            int i = tid + j * 256;              // < 1024
            int o = i >> 3, ch = i & 7;
            cp_async16(sdst + o * 128 + ((ch ^ (o & 7)) << 4),
                       Bsrc + (size_t)o * CIN + ch * 8);
        }
        CP_ASYNC_COMMIT();
    }

    // ---- build XS/XD (64 rows x 64 c, fp16 swizzled) from global x ----
    {
        const float4* xr4 = (const float4*)(xr + ((size_t)b * 128 + mhalf * 64) * CIN);
        const float4* xi4 = (const float4*)(xi + ((size_t)b * 128 + mhalf * 64) * CIN);
#pragma unroll 4
        for (int j = 0; j < 4; ++j) {
            int i4 = tid + j * 256;             // < 1024
            int row = i4 >> 4, cq = i4 & 15;
            float4 r = xr4[i4];
            float4 m = xi4[i4];
            uint2 hs = make_uint2(packh2(r.x + m.x, r.y + m.y), packh2(r.z + m.z, r.w + m.w));
            uint2 hd = make_uint2(packh2(m.x - r.x, m.y - r.y), packh2(m.z - r.z, m.w - r.w));
            uint32_t dst = row * 128 + (((cq >> 1) ^ (row & 7)) << 4) + (cq & 1) * 8;
            *(uint2*)(smem + SMX_XS + dst) = hs;
            *(uint2*)(smem + SMX_XD + dst) = hd;
        }
    }

    // ---- per-lane cf table ----
    uint32_t cf[4][2];
    {
        int r0 = mhalf * 64 + wm + (l >> 2);
        float c1a, s1a, c1b, s1b, c2a, s2a, c2b, s2b;
        sincospif((float)r0 * (1.0f / 64.0f), &s1a, &c1a);
        sincospif((float)(r0 + 8) * (1.0f / 64.0f), &s1b, &c1b);
        sincospif((float)r0 * (1.0f / 32.0f), &s2a, &c2a);
        sincospif((float)(r0 + 8) * (1.0f / 32.0f), &s2b, &c2b);
        cf[0][0] = bcasth2(c1a);  cf[0][1] = bcasth2(c1b);
        cf[1][0] = bcasth2(-s1a); cf[1][1] = bcasth2(-s1b);
        cf[2][0] = bcasth2(c2a);  cf[2][1] = bcasth2(c2b);
        cf[3][0] = bcasth2(-s2a); cf[3][1] = bcasth2(-s2b);
    }
    __syncthreads();                    // XS/XD visible

    // ---- A base fragments (loaded once) ----
    uint32_t ab[4][4];
    {
        const uint32_t xbase = sb + (v ? SMX_XD : SMX_XS);
        const int arow = wm + (l & 15);
        const uint32_t rowaddr = xbase + arow * 128;
        const int lxa = (l >> 4);
#pragma unroll 4
        for (int ks = 0; ks < 4; ++ks)
            ldsm4(ab[ks][0], ab[ks][1], ab[ks][2], ab[ks][3],
                  rowaddr + (((ks * 2 + lxa) ^ (arow & 7)) << 4));
    }

    float acc[16][4];
#pragma unroll
    for (int nt = 0; nt < 16; ++nt)
#pragma unroll
        for (int e = 0; e < 4; ++e) acc[nt][e] = 0.0f;

    const int nrowbase = (l & 15);
    const int lx = (l >> 4);

#pragma unroll 5
    for (int kb = 0; kb < 5; ++kb) {
        if (kb == 0) asm volatile("cp.async.wait_group 4;" ::: "memory");
        else if (kb == 1) asm volatile("cp.async.wait_group 3;" ::: "memory");
        else if (kb == 2) asm volatile("cp.async.wait_group 2;" ::: "memory");
        else if (kb == 3) asm volatile("cp.async.wait_group 1;" ::: "memory");
        else asm volatile("cp.async.wait_group 0;" ::: "memory");
        __syncthreads();                // stage kb visible CTA-wide
        const uint32_t bst = sb + SMX_B + kb * 16384;

#pragma unroll 4
        for (int ks = 0; ks < 4; ++ks) {
            uint32_t af[4];
            if (kb == 0) {
#pragma unroll
                for (int j = 0; j < 4; ++j) af[j] = ab[ks][j];
            } else {
#pragma unroll
                for (int j = 0; j < 4; ++j) af[j] = hmul2u(ab[ks][j], cf[kb - 1][j & 1]);
            }
#pragma unroll 2
            for (int half = 0; half < 2; ++half) {
                uint32_t bfr[8][2];
#pragma unroll 4
                for (int p = 0; p < 4; ++p) {
                    int nrow = (half * 4 + p) * 16 + nrowbase;
                    uint32_t addr = bst + nrow * 128 +
                                    (((ks * 2 + lx) ^ (nrow & 7)) << 4);
                    uint32_t q0, q1, q2, q3;
                    ldsm4(q0, q1, q2, q3, addr);
                    bfr[2 * p][0] = q0; bfr[2 * p][1] = q2;
                    bfr[2 * p + 1][0] = q1; bfr[2 * p + 1][1] = q3;
                }
#pragma unroll 8
                for (int nt = 0; nt < 8; ++nt)
                    mma16816(acc[half * 8 + nt], af, bfr[nt]);
            }
        }
    }

    // ---- epilogue: stage acc -> smem (padded), fused stats, coalesced streaming store ----
    __syncthreads();                    // everyone done reading B stages
    {
        char* stageV = smem + SMX_B + v * STG_VARB;
        const int rlo = wm + (l >> 2);
        float* sStatv = sStat + v * 256;
#pragma unroll 16
        for (int nt = 0; nt < 16; ++nt) {
            int c = nt * 8 + 2 * (l & 3);
            *(uint32_t*)(stageV + rlo * STG_ROWB + c * 2) = packh2(acc[nt][0], acc[nt][1]);
            *(uint32_t*)(stageV + (rlo + 8) * STG_ROWB + c * 2) = packh2(acc[nt][2], acc[nt][3]);
        }
#pragma unroll 16
        for (int nt = 0; nt < 16; ++nt) {
            int c = nt * 8 + 2 * (l & 3);
            float s0 = acc[nt][0] + acc[nt][2];
            float s1 = acc[nt][1] + acc[nt][3];
            float q0 = acc[nt][0] * acc[nt][0] + acc[nt][2] * acc[nt][2];
            float q1 = acc[nt][1] * acc[nt][1] + acc[nt][3] * acc[nt][3];
#pragma unroll
            for (int off = 4; off < 32; off <<= 1) {
                s0 += __shfl_xor_sync(0xFFFFFFFFu, s0, off);
                q0 += __shfl_xor_sync(0xFFFFFFFFu, q0, off);
                s1 += __shfl_xor_sync(0xFFFFFFFFu, s1, off);
                q1 += __shfl_xor_sync(0xFFFFFFFFu, q1, off);
            }
            if (l < 4) {
                atomicAdd(&sStatv[c], s0);
                atomicAdd(&sStatv[c + 1], s1);
                atomicAdd(&sStatv[128 + c], q0);
                atomicAdd(&sStatv[128 + c + 1], q1);
            }
        }
    }
    __syncthreads();                    // staging + stats complete

    // coalesced copy: per variant 64 rows x 256B; thread -> (row = tid>>2, part = tid&3)
    {
        const int row = tid >> 2;
        const int part = tid & 3;
#pragma unroll 2
        for (int v2 = 0; v2 < 2; ++v2) {
            const char* srow = smem + SMX_B + v2 * STG_VARB + row * STG_ROWB + part * 64;
            char* grow = (char*)(g_raw + ((size_t)v2 * ROWS_PER_VAR +
                                          (size_t)b * 128 + mhalf * 64 + row) * COUT) + part * 64;
#pragma unroll 4
            for (int k = 0; k < 4; ++k)
                stcs16(grow + k * 16, *(const uint4*)(srow + k * 16));
        }
    }

    atomicAdd(&g_sum[tid], sStat[(tid >> 7) * 256 + (tid & 127)]);
    atomicAdd(&g_sumsq[tid], sStat[(tid >> 7) * 256 + 128 + (tid & 127)]);
}

// ================= normalize: BN(train) + LeakyReLU, fp16 raw -> fp32 out =================
__global__ void __launch_bounds__(256) norm_kernel(float* __restrict__ out,
                                                   const float* __restrict__ gr,
                                                   const float* __restrict__ br,
                                                   const float* __restrict__ gi,
                                                   const float* __restrict__ bi) {
    __shared__ float sA[2 * COUT], sB[2 * COUT];
    const int tid = threadIdx.x;
    {
        int v = tid >> 7, o = tid & 127;
        const float inv = 1.0f / (float)ROWS_PER_VAR;
        float mean = g_sum[tid] * inv;
        float var  = g_sumsq[tid] * inv - mean * mean;
        float g  = v ? gi[o] : gr[o];
        float be = v ? bi[o] : br[o];
        float a = g * rsqrtf(var + EPS_BN);
        sA[tid] = a;
        sB[tid] = be - mean * a;
    }
    __syncthreads();

    const int vb = blockIdx.x >> 10;              // grid 2048: variant fixed per block
    const int base = (blockIdx.x & 1023) * 256 + tid;
    const int idx = vb * 128 + (tid & 15) * 8;    // channel block fixed per thread
    float cA[8], cB[8];
#pragma unroll 8
    for (int e = 0; e < 8; ++e) { cA[e] = sA[idx + e]; cB[e] = sB[idx + e]; }

    const uint4* rp = (const uint4*)g_raw + (size_t)vb * 2097152;
    float4* op = (float4*)out + (size_t)vb * 4194304;
#pragma unroll 8
    for (int k = 0; k < 8; ++k) {
        int i8 = base + k * 262144;               // < 2097152
        uint4 rv = ldcs16(rp + i8);
        float2 f0 = __half22float2(*(__half2*)&rv.x);
        float2 f1 = __half22float2(*(__half2*)&rv.y);
        float2 f2 = __half22float2(*(__half2*)&rv.z);
        float2 f3 = __half22float2(*(__half2*)&rv.w);
        float y0 = fmaf(cA[0], f0.x, cB[0]);
        float y1 = fmaf(cA[1], f0.y, cB[1]);
        float y2 = fmaf(cA[2], f1.x, cB[2]);
        float y3 = fmaf(cA[3], f1.y, cB[3]);
        float y4 = fmaf(cA[4], f2.x, cB[4]);
        float y5 = fmaf(cA[5], f2.y, cB[5]);
        float y6 = fmaf(cA[6], f3.x, cB[6]);
        float y7 = fmaf(cA[7], f3.y, cB[7]);
        y0 = y0 >= 0.f ? y0 : ALPHA * y0;
        y1 = y1 >= 0.f ? y1 : ALPHA * y1;
        y2 = y2 >= 0.f ? y2 : ALPHA * y2;
        y3 = y3 >= 0.f ? y3 : ALPHA * y3;
        y4 = y4 >= 0.f ? y4 : ALPHA * y4;
        y5 = y5 >= 0.f ? y5 : ALPHA * y5;
        y6 = y6 >= 0.f ? y6 : ALPHA * y6;
        y7 = y7 >= 0.f ? y7 : ALPHA * y7;
        float4 o0 = make_float4(y0, y1, y2, y3);
        float4 o1 = make_float4(y4, y5, y6, y7);
        stcs16(op + 2 * (size_t)i8, *(uint4*)&o0);
        stcs16(op + 2 * (size_t)i8 + 1, *(uint4*)&o1);
    }
}

// ================= launch =================
extern "C" void kernel_launch(void* const* d_in, const int* in_sizes, int n_in,
                              void* d_out, int out_size) {
    const float* xr = (const float*)d_in[0];
    const float* xi = (const float*)d_in[1];
    const float* fl = (const float*)d_in[2];
    const float* gr = (const float*)d_in[3];
    const float* br = (const float*)d_in[4];
    const float* gi = (const float*)d_in[5];
    const float* bi = (const float*)d_in[6];
    float* out = (float*)d_out;

    cudaFuncSetAttribute(fourier_main, cudaFuncAttributeMaxDynamicSharedMemorySize, SMX_TOTAL);

    prep_T<<<9, 256>>>(fl);
    prep_B2<<<5 * HH, 256>>>();
    fourier_main<<<2 * NB * HH, 256, SMX_TOTAL>>>(xr, xi);
    norm_kernel<<<2048, 256>>>(out, gr, br, gi, bi);
}

// round 10
// speedup vs baseline: 1.0950x; 1.0950x over previous
#include <cuda_runtime.h>
#include <cuda_fp16.h>
#include <cstdint>

// ---------------- problem dims ----------------
#define NB    8
#define HH    128
#define WW    128
#define CIN   64
#define COUT  128
#define ROWS_PER_VAR (NB*HH*WW)      // 131072
#define ALPHA 0.2f
#define EPS_BN 1e-3f

// ---------------- device globals (no allocs allowed) ----------------
__device__ __align__(16) float  g_fT[9 * COUT * CIN];                 // [uv][o][c] fp32
__device__ __align__(16) __half g_Bh[(size_t)HH * 5 * COUT * CIN];    // [h][vb][o][c] fp16
__device__ __align__(16) __half g_raw[(size_t)2 * ROWS_PER_VAR * COUT]; // fp16 raw GEMM out
__device__ float g_sum[2 * COUT];
__device__ float g_sumsq[2 * COUT];

// ---------------- helpers ----------------
__device__ __forceinline__ uint32_t smem_u32(const void* p) {
    uint32_t a;
    asm("{ .reg .u64 t; cvta.to.shared.u64 t, %1; cvt.u32.u64 %0, t; }" : "=r"(a) : "l"(p));
    return a;
}

__device__ __forceinline__ void ldsm4(uint32_t& r0, uint32_t& r1, uint32_t& r2, uint32_t& r3,
                                      uint32_t addr) {
    asm volatile("ldmatrix.sync.aligned.m8n8.x4.shared.b16 {%0,%1,%2,%3}, [%4];"
                 : "=r"(r0), "=r"(r1), "=r"(r2), "=r"(r3) : "r"(addr));
}

__device__ __forceinline__ void mma16816(float* d, const uint32_t* a, const uint32_t* b) {
    asm volatile("mma.sync.aligned.m16n8k16.row.col.f32.f16.f16.f32 "
                 "{%0,%1,%2,%3}, {%4,%5,%6,%7}, {%8,%9}, {%0,%1,%2,%3};"
                 : "+f"(d[0]), "+f"(d[1]), "+f"(d[2]), "+f"(d[3])
                 : "r"(a[0]), "r"(a[1]), "r"(a[2]), "r"(a[3]), "r"(b[0]), "r"(b[1]));
}

__device__ __forceinline__ uint32_t packh2(float lo, float hi) {
    __half2 t = __floats2half2_rn(lo, hi);
    return *(uint32_t*)&t;
}

__device__ __forceinline__ uint32_t bcasth2(float x) {
    __half h = __float2half_rn(x);
    __half2 t = __half2half2(h);
    return *(uint32_t*)&t;
}

__device__ __forceinline__ uint32_t hmul2u(uint32_t a, uint32_t b) {
    __half2 r = __hmul2(*(__half2*)&a, *(__half2*)&b);
    return *(uint32_t*)&r;
}

__device__ __forceinline__ void cp_async16(uint32_t dst_smem, const void* src) {
    asm volatile("cp.async.cg.shared.global [%0], [%1], 16;"
                 :: "r"(dst_smem), "l"(src) : "memory");
}
#define CP_ASYNC_COMMIT() asm volatile("cp.async.commit_group;" ::: "memory")

// ================= prep 1: transpose filters [uv][c][o] -> g_fT[uv][o][c]; zero stats =====
__global__ void __launch_bounds__(256) prep_T(const float* __restrict__ filters) {
    __shared__ float tile[COUT * 65];
    const int uv = blockIdx.x;          // 0..8
    const int tid = threadIdx.x;
    if (uv == 0) { g_sum[tid] = 0.0f; g_sumsq[tid] = 0.0f; }
    const float* src = filters + (size_t)uv * (CIN * COUT);
#pragma unroll 32
    for (int j = 0; j < 32; ++j) {
        int idx = tid + j * 256;
        tile[(idx & 127) * 65 + (idx >> 7)] = src[idx];
    }
    __syncthreads();
    float* dst = g_fT + (size_t)uv * (COUT * CIN);
#pragma unroll 32
    for (int j = 0; j < 32; ++j) {
        int idx = tid + j * 256;
        dst[idx] = tile[(idx >> 6) * 65 + (idx & 63)];
    }
}

// ================= prep 2: stream per-(h, basis) matrices to fp16 ==================
__global__ void __launch_bounds__(256) prep_B2() {
    const int hb = blockIdx.x;          // h*5 + vb
    const int h = hb / 5;
    const int vb = hb - 5 * h;
    const int tid = threadIdx.x;
    const int v = (vb == 0) ? 0 : ((vb <= 2) ? 1 : 2);
    const bool sinb = (vb == 2) || (vb == 4);

    float c1, s1, c2, s2;
    sincospif((float)h * (1.0f / 64.0f), &s1, &c1);
    sincospif((float)h * (1.0f / 32.0f), &s2, &c2);
    const float w0 = sinb ? 0.0f : 1.0f;
    const float w1 = sinb ? s1 : c1;
    const float w2 = sinb ? s2 : c2;

    const float4* p0 = (const float4*)(g_fT + (size_t)(0 * 3 + v) * (COUT * CIN));
    const float4* p1 = (const float4*)(g_fT + (size_t)(1 * 3 + v) * (COUT * CIN));
    const float4* p2 = (const float4*)(g_fT + (size_t)(2 * 3 + v) * (COUT * CIN));
    __half* dst = g_Bh + (size_t)hb * (COUT * CIN);

#pragma unroll 4
    for (int j = 0; j < 4; ++j) {
        int g = tid + j * 256;
        int f4 = g * 2;
#pragma unroll 2
        for (int q = 0; q < 2; ++q) {
            float4 a = p0[f4 + q];
            float4 b = p1[f4 + q];
            float4 c = p2[f4 + q];
            float r0 = w0 * a.x + w1 * b.x + w2 * c.x;
            float r1 = w0 * a.y + w1 * b.y + w2 * c.y;
            float r2 = w0 * a.z + w1 * b.z + w2 * c.z;
            float r3 = w0 * a.w + w1 * b.w + w2 * c.w;
            *(uint2*)(dst + (size_t)g * 8 + q * 4) =
                make_uint2(packh2(r0, r1), packh2(r2, r3));
        }
    }
}

// ---------------- main smem layout ----------------
#define SMX_XS    0          // 64 rows x 128B fp16 swizzled (sum variant)   = 8192
#define SMX_XD    8192       // 64 rows x 128B fp16 swizzled (dif variant)   = 8192
#define SMX_B     16384      // 3 stages x (128 rows x 128B)                 = 49152
#define SMX_STAT  65536      // 512 floats                                   = 2048
#define SMX_TOTAL 67584

// issue one B stage (16 KB) via cp.async, swizzled
__device__ __forceinline__ void issue_B_stage(uint32_t sb, const __half* BhBase,
                                              int s, int tid) {
    const __half* Bsrc = BhBase + (size_t)s * (COUT * CIN);
    uint32_t sdst = sb + SMX_B + (s % 3) * 16384;
#pragma unroll 4
    for (int j = 0; j < 4; ++j) {
        int i = tid + j * 256;              // < 1024
        int o = i >> 3, ch = i & 7;
        cp_async16(sdst + o * 128 + ((ch ^ (o & 7)) << 4),
                   Bsrc + (size_t)o * CIN + ch * 8);
    }
    CP_ASYNC_COMMIT();
}

// ================= main: per CTA = (n,h, M-half); 3-stage pipeline, 1 sync/kb =============
__global__ void __launch_bounds__(256, 2) fourier_main(const float* __restrict__ xr,
                                                       const float* __restrict__ xi) {
    extern __shared__ char smem[];
    float* sStat = (float*)(smem + SMX_STAT);
    const uint32_t sb = smem_u32(smem);

    const int tid = threadIdx.x;
    const int wid = tid >> 5;
    const int l = tid & 31;
    const int v = wid >> 2;             // 0 = real(sum), 1 = imag(dif)
    const int wm = (wid & 3) * 16;      // warp M tile within the 64-row half
    const int bid = blockIdx.x;
    const int b = bid >> 1;             // n*128 + h
    const int mhalf = bid & 1;
    const int h = b & 127;

    sStat[tid] = 0.0f;
    sStat[tid + 256] = 0.0f;

    // ---- prologue: prefetch B stages 0 and 1 only ----
    const __half* BhBase = g_Bh + (size_t)(h * 5) * (COUT * CIN);
    issue_B_stage(sb, BhBase, 0, tid);
    issue_B_stage(sb, BhBase, 1, tid);

    // ---- build XS/XD (64 rows x 64 c, fp16 swizzled) from global x ----
    {
        const float4* xr4 = (const float4*)(xr + ((size_t)b * 128 + mhalf * 64) * CIN);
        const float4* xi4 = (const float4*)(xi + ((size_t)b * 128 + mhalf * 64) * CIN);
#pragma unroll 4
        for (int j = 0; j < 4; ++j) {
            int i4 = tid + j * 256;             // < 1024
            int row = i4 >> 4, cq = i4 & 15;
            float4 r = xr4[i4];
            float4 m = xi4[i4];
            uint2 hs = make_uint2(packh2(r.x + m.x, r.y + m.y), packh2(r.z + m.z, r.w + m.w));
            uint2 hd = make_uint2(packh2(m.x - r.x, m.y - r.y), packh2(m.z - r.z, m.w - r.w));
            uint32_t dst = row * 128 + (((cq >> 1) ^ (row & 7)) << 4) + (cq & 1) * 8;
            *(uint2*)(smem + SMX_XS + dst) = hs;
            *(uint2*)(smem + SMX_XD + dst) = hd;
        }
    }

    // ---- per-lane cf table ----
    uint32_t cf[4][2];
    {
        int r0 = mhalf * 64 + wm + (l >> 2);
        float c1a, s1a, c1b, s1b, c2a, s2a, c2b, s2b;
        sincospif((float)r0 * (1.0f / 64.0f), &s1a, &c1a);
        sincospif((float)(r0 + 8) * (1.0f / 64.0f), &s1b, &c1b);
        sincospif((float)r0 * (1.0f / 32.0f), &s2a, &c2a);
        sincospif((float)(r0 + 8) * (1.0f / 32.0f), &s2b, &c2b);
        cf[0][0] = bcasth2(c1a);  cf[0][1] = bcasth2(c1b);
        cf[1][0] = bcasth2(-s1a); cf[1][1] = bcasth2(-s1b);
        cf[2][0] = bcasth2(c2a);  cf[2][1] = bcasth2(c2b);
        cf[3][0] = bcasth2(-s2a); cf[3][1] = bcasth2(-s2b);
    }
    __syncthreads();                    // XS/XD visible

    // ---- A base fragments (loaded once) ----
    uint32_t ab[4][4];
    {
        const uint32_t xbase = sb + (v ? SMX_XD : SMX_XS);
        const int arow = wm + (l & 15);
        const uint32_t rowaddr = xbase + arow * 128;
        const int lxa = (l >> 4);
#pragma unroll 4
        for (int ks = 0; ks < 4; ++ks)
            ldsm4(ab[ks][0], ab[ks][1], ab[ks][2], ab[ks][3],
                  rowaddr + (((ks * 2 + lxa) ^ (arow & 7)) << 4));
    }

    float acc[16][4];
#pragma unroll
    for (int nt = 0; nt < 16; ++nt)
#pragma unroll
        for (int e = 0; e < 4; ++e) acc[nt][e] = 0.0f;

    const int nrowbase = (l & 15);
    const int lx = (l >> 4);

#pragma unroll 5
    for (int kb = 0; kb < 5; ++kb) {
        // stage kb ready: allow exactly the groups after it to be pending
        if (kb < 4) asm volatile("cp.async.wait_group 1;" ::: "memory");
        else        asm volatile("cp.async.wait_group 0;" ::: "memory");
        __syncthreads();                // stage kb visible; buffer (kb+2)%3 free
        if (kb + 2 < 5) issue_B_stage(sb, BhBase, kb + 2, tid);

        const uint32_t bst = sb + SMX_B + (kb % 3) * 16384;

#pragma unroll 4
        for (int ks = 0; ks < 4; ++ks) {
            uint32_t af[4];
            if (kb == 0) {
#pragma unroll
                for (int j = 0; j < 4; ++j) af[j] = ab[ks][j];
            } else {
#pragma unroll
                for (int j = 0; j < 4; ++j) af[j] = hmul2u(ab[ks][j], cf[kb - 1][j & 1]);
            }
#pragma unroll 2
            for (int half = 0; half < 2; ++half) {
                uint32_t bfr[8][2];
#pragma unroll 4
                for (int p = 0; p < 4; ++p) {
                    int nrow = (half * 4 + p) * 16 + nrowbase;
                    uint32_t addr = bst + nrow * 128 +
                                    (((ks * 2 + lx) ^ (nrow & 7)) << 4);
                    uint32_t q0, q1, q2, q3;
                    ldsm4(q0, q1, q2, q3, addr);
                    bfr[2 * p][0] = q0; bfr[2 * p][1] = q2;
                    bfr[2 * p + 1][0] = q1; bfr[2 * p + 1][1] = q3;
                }
#pragma unroll 8
                for (int nt = 0; nt < 8; ++nt)
                    mma16816(acc[half * 8 + nt], af, bfr[nt]);
            }
        }
    }

    // ---- epilogue: fp16 raw store + fused stats (R6-proven direct form) ----
    {
        __half* rbase = g_raw + ((size_t)v * ROWS_PER_VAR + (size_t)b * 128 + mhalf * 64) * COUT;
        const int rlo = wm + (l >> 2);
        float* sStatv = sStat + v * 256;
#pragma unroll 16
        for (int nt = 0; nt < 16; ++nt) {
            int c = nt * 8 + 2 * (l & 3);
            *(uint32_t*)(rbase + (size_t)rlo * COUT + c) = packh2(acc[nt][0], acc[nt][1]);
            *(uint32_t*)(rbase + (size_t)(rlo + 8) * COUT + c) = packh2(acc[nt][2], acc[nt][3]);
            float s0 = acc[nt][0] + acc[nt][2];
            float s1 = acc[nt][1] + acc[nt][3];
            float q0 = acc[nt][0] * acc[nt][0] + acc[nt][2] * acc[nt][2];
            float q1 = acc[nt][1] * acc[nt][1] + acc[nt][3] * acc[nt][3];
#pragma unroll
            for (int off = 4; off < 32; off <<= 1) {
                s0 += __shfl_xor_sync(0xFFFFFFFFu, s0, off);
                q0 += __shfl_xor_sync(0xFFFFFFFFu, q0, off);
                s1 += __shfl_xor_sync(0xFFFFFFFFu, s1, off);
                q1 += __shfl_xor_sync(0xFFFFFFFFu, q1, off);
            }
            if (l < 4) {
                atomicAdd(&sStatv[c], s0);
                atomicAdd(&sStatv[c + 1], s1);
                atomicAdd(&sStatv[128 + c], q0);
                atomicAdd(&sStatv[128 + c + 1], q1);
            }
        }
    }

    __syncthreads();
    atomicAdd(&g_sum[tid], sStat[(tid >> 7) * 256 + (tid & 127)]);
    atomicAdd(&g_sumsq[tid], sStat[(tid >> 7) * 256 + 128 + (tid & 127)]);
}

// ================= normalize: BN(train) + LeakyReLU, fp16 raw -> fp32 out =================
__global__ void __launch_bounds__(256) norm_kernel(float* __restrict__ out,
                                                   const float* __restrict__ gr,
                                                   const float* __restrict__ br,
                                                   const float* __restrict__ gi,
                                                   const float* __restrict__ bi) {
    __shared__ float sA[2 * COUT], sB[2 * COUT];
    const int tid = threadIdx.x;
    {
        int v = tid >> 7, o = tid & 127;
        const float inv = 1.0f / (float)ROWS_PER_VAR;
        float mean = g_sum[tid] * inv;
        float var  = g_sumsq[tid] * inv - mean * mean;
        float g  = v ? gi[o] : gr[o];
        float be = v ? bi[o] : br[o];
        float a = g * rsqrtf(var + EPS_BN);
        sA[tid] = a;
        sB[tid] = be - mean * a;
    }
    __syncthreads();

    const int vb = blockIdx.x >> 11;              // grid 4096: variant fixed per block
    const int base = (blockIdx.x & 2047) * 256 + tid;
    const int idx = vb * 128 + (tid & 15) * 8;    // channel block fixed per thread
    float cA[8], cB[8];
#pragma unroll 8
    for (int e = 0; e < 8; ++e) { cA[e] = sA[idx + e]; cB[e] = sB[idx + e]; }

    const uint4* rp = (const uint4*)g_raw + (size_t)vb * 2097152;
    float4* op = (float4*)out + (size_t)vb * 4194304;
#pragma unroll 4
    for (int k = 0; k < 4; ++k) {
        int i8 = base + k * 524288;               // < 2097152
        uint4 rv = rp[i8];
        float2 f0 = __half22float2(*(__half2*)&rv.x);
        float2 f1 = __half22float2(*(__half2*)&rv.y);
        float2 f2 = __half22float2(*(__half2*)&rv.z);
        float2 f3 = __half22float2(*(__half2*)&rv.w);
        float y0 = fmaf(cA[0], f0.x, cB[0]);
        float y1 = fmaf(cA[1], f0.y, cB[1]);
        float y2 = fmaf(cA[2], f1.x, cB[2]);
        float y3 = fmaf(cA[3], f1.y, cB[3]);
        float y4 = fmaf(cA[4], f2.x, cB[4]);
        float y5 = fmaf(cA[5], f2.y, cB[5]);
        float y6 = fmaf(cA[6], f3.x, cB[6]);
        float y7 = fmaf(cA[7], f3.y, cB[7]);
        y0 = y0 >= 0.f ? y0 : ALPHA * y0;
        y1 = y1 >= 0.f ? y1 : ALPHA * y1;
        y2 = y2 >= 0.f ? y2 : ALPHA * y2;
        y3 = y3 >= 0.f ? y3 : ALPHA * y3;
        y4 = y4 >= 0.f ? y4 : ALPHA * y4;
        y5 = y5 >= 0.f ? y5 : ALPHA * y5;
        y6 = y6 >= 0.f ? y6 : ALPHA * y6;
        y7 = y7 >= 0.f ? y7 : ALPHA * y7;
        float4* o4 = op + 2 * (size_t)i8;
        o4[0] = make_float4(y0, y1, y2, y3);
        o4[1] = make_float4(y4, y5, y6, y7);
    }
}

// ================= launch =================
extern "C" void kernel_launch(void* const* d_in, const int* in_sizes, int n_in,
                              void* d_out, int out_size) {
    const float* xr = (const float*)d_in[0];
    const float* xi = (const float*)d_in[1];
    const float* fl = (const float*)d_in[2];
    const float* gr = (const float*)d_in[3];
    const float* br = (const float*)d_in[4];
    const float* gi = (const float*)d_in[5];
    const float* bi = (const float*)d_in[6];
    float* out = (float*)d_out;

    cudaFuncSetAttribute(fourier_main, cudaFuncAttributeMaxDynamicSharedMemorySize, SMX_TOTAL);

    prep_T<<<9, 256>>>(fl);
    prep_B2<<<5 * HH, 256>>>();
    fourier_main<<<2 * NB * HH, 256, SMX_TOTAL>>>(xr, xi);
    norm_kernel<<<4096, 256>>>(out, gr, br, gi, bi);
}